// round 13
// baseline (speedup 1.0000x reference)
#include <cuda_runtime.h>
#include <cuda_bf16.h>
#include <cstdint>

#define BDIM 8
#define CDIM 256
#define NDIM 4096
#define BT   128
#define KB   16

// ---------------- device scratch (allocation-free rule) ----------------
__device__ __align__(1024) float g_MT[CDIM * CDIM];                         // MT[k][c]
__device__ __align__(1024) __nv_bfloat16 g_Yhi[(size_t)BDIM * NDIM * CDIM]; // Yt hi: [b][m][c]
__device__ __align__(1024) __nv_bfloat16 g_Ylo[(size_t)BDIM * NDIM * CDIM]; // Yt lo
__device__ __align__(1024) __nv_bfloat16 g_Xhi[(size_t)BDIM * NDIM * CDIM]; // Xt hi: [b][n][c]
__device__ __align__(1024) __nv_bfloat16 g_Xlo[(size_t)BDIM * NDIM * CDIM]; // Xt lo

// ---------------- helpers ----------------
__device__ __forceinline__ void cp16(uint32_t s, const void* g) {
    asm volatile("cp.async.cg.shared.global [%0], [%1], 16;" :: "r"(s), "l"(g));
}
__device__ __forceinline__ void cp_commit() { asm volatile("cp.async.commit_group;"); }
__device__ __forceinline__ void cp_wait0()  { asm volatile("cp.async.wait_group 0;"); }
__device__ __forceinline__ void cp_wait1()  { asm volatile("cp.async.wait_group 1;"); }

__device__ __forceinline__ unsigned long long dup2(float x) {
    unsigned long long r;
    asm("mov.b64 %0, {%1, %1};" : "=l"(r) : "f"(x));
    return r;
}
__device__ __forceinline__ void ffma2(unsigned long long& d, unsigned long long a, unsigned long long b) {
    asm("fma.rn.f32x2 %0, %1, %2, %0;" : "+l"(d) : "l"(a), "l"(b));
}
__device__ __forceinline__ float lo32(unsigned long long v) { return __uint_as_float((unsigned int)v); }
__device__ __forceinline__ float hi32(unsigned long long v) { return __uint_as_float((unsigned int)(v >> 32)); }

__device__ __forceinline__ unsigned short f2bf(float x) {
    return __bfloat16_as_ushort(__float2bfloat16(x));
}
__device__ __forceinline__ float bf2f(unsigned short u) {
    __nv_bfloat16_raw r; r.x = u;
    return __bfloat162float(__nv_bfloat16(r));
}
__device__ __forceinline__ uint32_t smem_u32(const void* p) {
    uint32_t a;
    asm("{ .reg .u64 t; cvta.to.shared.u64 t, %1; cvt.u32.u64 %0, t; }" : "=r"(a) : "l"(p));
    return a;
}

// ---------------- tensor-core primitives (plain sm_103-safe: sm_80 era) ----------------
__device__ __forceinline__ void ldsm4(uint32_t* r, uint32_t addr) {
    asm volatile("ldmatrix.sync.aligned.m8n8.x4.shared.b16 {%0,%1,%2,%3}, [%4];"
        : "=r"(r[0]), "=r"(r[1]), "=r"(r[2]), "=r"(r[3]) : "r"(addr));
}
__device__ __forceinline__ void mma_bf16(float* d, const uint32_t* a, const uint32_t* b) {
    asm volatile("mma.sync.aligned.m16n8k16.row.col.f32.bf16.bf16.f32 "
        "{%0,%1,%2,%3}, {%4,%5,%6,%7}, {%8,%9}, {%0,%1,%2,%3};"
        : "+f"(d[0]), "+f"(d[1]), "+f"(d[2]), "+f"(d[3])
        : "r"(a[0]), "r"(a[1]), "r"(a[2]), "r"(a[3]), "r"(b[0]), "r"(b[1]));
}

// ---------------- kernel A: MT fold ----------------
__global__ void mt_kernel(const float* __restrict__ Wq, const float* __restrict__ Wk) {
    __shared__ float Qs[16][16];
    __shared__ float Ks[16][16];
    const int tx = threadIdx.x, ty = threadIdx.y;
    const int c = blockIdx.x * 16 + tx;
    const int k = blockIdx.y * 16 + ty;
    float acc = 0.f;
    for (int d0 = 0; d0 < CDIM; d0 += 16) {
        Qs[ty][tx] = Wq[(d0 + ty) * CDIM + blockIdx.x * 16 + tx];
        Ks[ty][tx] = Wk[(d0 + ty) * CDIM + blockIdx.y * 16 + tx];
        __syncthreads();
#pragma unroll
        for (int dd = 0; dd < 16; dd++) acc += Qs[dd][tx] * Ks[dd][ty];
        __syncthreads();
    }
    g_MT[k * CDIM + c] = acc;
}

// ---------------- kernel A2: Xt split transpose ----------------
__global__ void xt_kernel(const float* __restrict__ X) {
    __shared__ float s[32][33];
    const int b = blockIdx.z;
    const int n0 = blockIdx.x * 32, c0 = blockIdx.y * 32;
    const float* Xb = X + (size_t)b * CDIM * NDIM;
    const int tx = threadIdx.x, ty = threadIdx.y;
#pragma unroll
    for (int i = 0; i < 4; i++)
        s[ty + 8 * i][tx] = Xb[(size_t)(c0 + ty + 8 * i) * NDIM + n0 + tx];
    __syncthreads();
#pragma unroll
    for (int i = 0; i < 4; i++) {
        float v = s[tx][ty + 8 * i];
        unsigned short h = f2bf(v);
        unsigned short l = f2bf(v - bf2f(h));
        size_t off = ((size_t)b * NDIM + n0 + ty + 8 * i) * CDIM + c0 + tx;
        ((unsigned short*)g_Xhi)[off] = h;
        ((unsigned short*)g_Xlo)[off] = l;
    }
}

// ---------------- kernel B: Y = M X, written TRANSPOSED as bf16 hi/lo splits ----------------
__global__ __launch_bounds__(256, 2) void ymat_kernel(const float* __restrict__ X) {
    const int b  = blockIdx.z;
    const int m0 = blockIdx.x * BT;
    const int c0 = blockIdx.y * BT;
    const float* Xb = X + (size_t)b * CDIM * NDIM;

    __shared__ float As[2][KB][BT];
    __shared__ float Bs[2][KB][BT];

    const int tid = threadIdx.x;
    const int tx = tid & 15, ty = tid >> 4;
    const int kk0 = tid >> 5;
    const int c4 = (tid & 31) * 4;

    uint32_t aAddr0 = (uint32_t)__cvta_generic_to_shared(&As[0][kk0][c4]);
    uint32_t bAddr0 = (uint32_t)__cvta_generic_to_shared(&Bs[0][kk0][c4]);
    const uint32_t bufStride = (uint32_t)(KB * BT * 4);
    const uint32_t rowOff = 8 * BT * 4;

    const float* gA0 = g_MT + kk0 * CDIM + c0 + c4;
    const float* gB0 = Xb + kk0 * NDIM + m0 + c4;

    cp16(aAddr0, gA0);
    cp16(aAddr0 + rowOff, gA0 + 8 * CDIM);
    cp16(bAddr0, gB0);
    cp16(bAddr0 + rowOff, gB0 + 8 * NDIM);
    cp_commit();

    unsigned long long acc[8][4];
#pragma unroll
    for (int i = 0; i < 8; i++)
#pragma unroll
        for (int j = 0; j < 4; j++) acc[i][j] = 0ull;

    const int NKC = CDIM / KB;
#pragma unroll 1
    for (int kc = 0; kc < NKC; kc++) {
        if (kc + 1 < NKC) {
            uint32_t boff = (uint32_t)((kc + 1) & 1) * bufStride;
            const float* ga = gA0 + (kc + 1) * KB * CDIM;
            const float* gb = gB0 + (kc + 1) * KB * NDIM;
            cp16(aAddr0 + boff, ga);
            cp16(aAddr0 + boff + rowOff, ga + 8 * CDIM);
            cp16(bAddr0 + boff, gb);
            cp16(bAddr0 + boff + rowOff, gb + 8 * NDIM);
            cp_commit();
            cp_wait1();
        } else {
            cp_wait0();
        }
        __syncthreads();
        const float (*Ac)[BT] = As[kc & 1];
        const float (*Bc)[BT] = Bs[kc & 1];
#pragma unroll
        for (int kk = 0; kk < KB; kk++) {
            float4 a0 = *(const float4*)&Ac[kk][ty * 8];
            float4 a1 = *(const float4*)&Ac[kk][ty * 8 + 4];
            ulonglong2 b0 = *(const ulonglong2*)&Bc[kk][tx * 8];
            ulonglong2 b1 = *(const ulonglong2*)&Bc[kk][tx * 8 + 4];
            unsigned long long bp0 = b0.x, bp1 = b0.y, bp2 = b1.x, bp3 = b1.y;
            float av[8] = {a0.x, a0.y, a0.z, a0.w, a1.x, a1.y, a1.z, a1.w};
#pragma unroll
            for (int i = 0; i < 8; i++) {
                unsigned long long ai = dup2(av[i]);
                ffma2(acc[i][0], ai, bp0);
                ffma2(acc[i][1], ai, bp1);
                ffma2(acc[i][2], ai, bp2);
                ffma2(acc[i][3], ai, bp3);
            }
        }
        __syncthreads();
    }

    // Transposed split write: Yt[b][m][c] hi/lo bf16.
#pragma unroll
    for (int jj = 0; jj < 8; jj++) {
        uint32_t hw[4], lw[4];
#pragma unroll
        for (int p = 0; p < 4; p++) {
            float v0 = (jj & 1) ? hi32(acc[2 * p][jj >> 1])     : lo32(acc[2 * p][jj >> 1]);
            float v1 = (jj & 1) ? hi32(acc[2 * p + 1][jj >> 1]) : lo32(acc[2 * p + 1][jj >> 1]);
            unsigned short h0 = f2bf(v0), h1 = f2bf(v1);
            unsigned short l0 = f2bf(v0 - bf2f(h0)), l1 = f2bf(v1 - bf2f(h1));
            hw[p] = (uint32_t)h0 | ((uint32_t)h1 << 16);
            lw[p] = (uint32_t)l0 | ((uint32_t)l1 << 16);
        }
        size_t row = (size_t)b * NDIM + (m0 + tx * 8 + jj);
        uint4* dh = (uint4*)(g_Yhi + row * CDIM + c0 + ty * 8);
        uint4* dl = (uint4*)(g_Ylo + row * CDIM + c0 + ty * 8);
        *dh = make_uint4(hw[0], hw[1], hw[2], hw[3]);
        *dl = make_uint4(lw[0], lw[1], lw[2], lw[3]);
    }
}

// ---------------- kernel C: mma.sync flash row-stats, 8 compute warps + 3-stage ring ----------------
// SMEM: Ahi[128][512B] @0 (64KB), Alo @65536 (64KB),
//       B ring @131072: slot s(0..2)*32768 + comp*16384, rows 32 x 512B  (96KB)
//       sdiag @229376 (512B), sfac @229888 (512B). Total 230400.
#define SM_ALO   65536u
#define SM_B     131072u
#define SM_SDIAG 229376u
#define SM_SFAC  229888u
#define SMEM_SZ  230400

__device__ __forceinline__ uint32_t a_addr(uint32_t sb, int comp, int row, int kc, int L) {
    int r = row + (L & 15);
    int kh = (L >> 4) & 1;
    return sb + (uint32_t)comp * SM_ALO + (uint32_t)(r * 512 + ((kc ^ (r & 7)) * 32) + kh * 16);
}
__device__ __forceinline__ uint32_t b_addr(uint32_t sb, int comp, int slot, int p, int kc, int L) {
    int r = p * 16 + (L & 7) + (((L >> 4) & 1) << 3);
    int kh = (L >> 3) & 1;
    return sb + SM_B + (uint32_t)slot * 32768u + (uint32_t)comp * 16384u +
           (uint32_t)(r * 512 + ((kc ^ (r & 7)) * 32) + kh * 16);
}

__global__ __launch_bounds__(384, 1) void attn_kernel(const float* __restrict__ X,
                                                      float* __restrict__ out) {
    extern __shared__ __align__(1024) char smem[];
    const uint32_t sb = smem_u32(smem);
    const int tid = threadIdx.x;
    const int L = tid & 31;
    const int w = tid >> 5;           // 0..11; 0-7 compute, 8-11 load
    const int b  = blockIdx.y;
    const int n0 = blockIdx.x * 128;

    const float* Xb = X + (size_t)b * CDIM * NDIM;
    float* sdiag = (float*)(smem + SM_SDIAG);
    float* sfac  = (float*)(smem + SM_SFAC);

    // ---- prologue: load A (Xt hi/lo) with swizzle, all 384 threads ----
    for (int i = tid; i < 8192; i += 384) {
        int comp = i >> 12;
        int rem = i & 4095;
        int r = rem >> 5, u = rem & 31;
        const __nv_bfloat16* src =
            (comp ? g_Xlo : g_Xhi) + ((size_t)b * NDIM + n0 + r) * CDIM + u * 8;
        uint32_t dst = sb + (uint32_t)comp * SM_ALO +
                       (uint32_t)(r * 512 + (((u >> 1) ^ (r & 7)) * 32) + (u & 1) * 16);
        cp16(dst, src);
    }
    cp_commit();
    cp_wait0();
    __syncthreads();

    // ---- diag (tid<128) + B ring prefetch of stages 0,1 (loader warps) ----
    if (tid < 128) {
        const int r = tid;
        const uint4* yh = (const uint4*)(g_Yhi + ((size_t)b * NDIM + n0 + r) * CDIM);
        const uint4* yl = (const uint4*)(g_Ylo + ((size_t)b * NDIM + n0 + r) * CDIM);
        float dg = 0.f;
#pragma unroll 4
        for (int u = 0; u < 32; u++) {
            uint32_t off = (uint32_t)(r * 512 + (((u >> 1) ^ (r & 7)) * 32) + (u & 1) * 16);
            uint4 xh = *(const uint4*)(smem + off);
            uint4 xl = *(const uint4*)(smem + SM_ALO + off);
            uint4 vh = yh[u], vl = yl[u];
            const uint32_t* ph = (const uint32_t*)&xh;
            const uint32_t* pl = (const uint32_t*)&xl;
            const uint32_t* qh = (const uint32_t*)&vh;
            const uint32_t* ql = (const uint32_t*)&vl;
#pragma unroll
            for (int ww = 0; ww < 4; ww++) {
                float x0 = bf2f((unsigned short)(ph[ww] & 0xffff)) + bf2f((unsigned short)(pl[ww] & 0xffff));
                float x1 = bf2f((unsigned short)(ph[ww] >> 16))    + bf2f((unsigned short)(pl[ww] >> 16));
                float y0 = bf2f((unsigned short)(qh[ww] & 0xffff)) + bf2f((unsigned short)(ql[ww] & 0xffff));
                float y1 = bf2f((unsigned short)(qh[ww] >> 16))    + bf2f((unsigned short)(ql[ww] >> 16));
                dg = fmaf(x0, y0, dg);
                dg = fmaf(x1, y1, dg);
            }
        }
        sdiag[r] = dg;
    } else if (tid >= 256) {
        const int lt = tid - 256;   // 0..127
#pragma unroll 1
        for (int st = 0; st < 2; st++) {
            for (int i = lt; i < 2048; i += 128) {
                int comp = i >> 10;
                int rem = i & 1023;
                int r = rem >> 5, u = rem & 31;
                const __nv_bfloat16* src =
                    (comp ? g_Ylo : g_Yhi) + ((size_t)b * NDIM + st * 32 + r) * CDIM + u * 8;
                uint32_t dst = sb + SM_B + (uint32_t)st * 32768u + (uint32_t)comp * 16384u +
                               (uint32_t)(r * 512 + (((u >> 1) ^ (r & 7)) * 32) + (u & 1) * 16);
                cp16(dst, src);
            }
            cp_commit();
        }
    }

    // ---- mainloop over 128 m-tiles of 32, prefetch depth 2 / 3-slot ring ----
    const int NIT = NDIM / 32;  // 128
    float mrun[2], srun[2];
    mrun[0] = mrun[1] = -1e30f;
    srun[0] = srun[1] = 0.f;

#pragma unroll 1
    for (int it = 0; it < NIT; it++) {
        if (tid >= 256) {
            if (it + 1 < NIT) cp_wait1(); else cp_wait0();  // stage `it` landed
        }
        __syncthreads();

        if (tid >= 256) {
            // issue stage it+2 into ring slot (it+2)%3 (freed: compute of it-1 done)
            if (it + 2 < NIT) {
                const int lt = tid - 256;
                const int mb = (it + 2) * 32;
                const int slot = (it + 2) % 3;
                for (int i = lt; i < 2048; i += 128) {
                    int comp = i >> 10;
                    int rem = i & 1023;
                    int r = rem >> 5, u = rem & 31;
                    const __nv_bfloat16* src =
                        (comp ? g_Ylo : g_Yhi) + ((size_t)b * NDIM + mb + r) * CDIM + u * 8;
                    uint32_t dst = sb + SM_B + (uint32_t)slot * 32768u + (uint32_t)comp * 16384u +
                                   (uint32_t)(r * 512 + (((u >> 1) ^ (r & 7)) * 32) + (u & 1) * 16);
                    cp16(dst, src);
                }
                cp_commit();
            }
        } else {
            // ---- compute warp w (0..7): D[16n x 32m], rows n0 + w*16.. ----
            const int slot = it % 3;
            float acc[4][4];
#pragma unroll
            for (int bt = 0; bt < 4; bt++)
#pragma unroll
                for (int q = 0; q < 4; q++) acc[bt][q] = 0.f;

#pragma unroll 2
            for (int kc = 0; kc < 16; kc++) {
                uint32_t AH[4], AL[4], BH[2][4], BL[2][4];
                ldsm4(AH, a_addr(sb, 0, w * 16, kc, L));
                ldsm4(BH[0], b_addr(sb, 0, slot, 0, kc, L));
                ldsm4(BH[1], b_addr(sb, 0, slot, 1, kc, L));
                ldsm4(AL, a_addr(sb, 1, w * 16, kc, L));
                ldsm4(BL[0], b_addr(sb, 1, slot, 0, kc, L));
                ldsm4(BL[1], b_addr(sb, 1, slot, 1, kc, L));
#pragma unroll
                for (int bt = 0; bt < 4; bt++)
                    mma_bf16(acc[bt], AH, &BH[bt >> 1][(bt & 1) * 2]);
#pragma unroll
                for (int bt = 0; bt < 4; bt++)
                    mma_bf16(acc[bt], AH, &BL[bt >> 1][(bt & 1) * 2]);
#pragma unroll
                for (int bt = 0; bt < 4; bt++)
                    mma_bf16(acc[bt], AL, &BH[bt >> 1][(bt & 1) * 2]);
            }

            // ---- online softmax: 2 rows x 8 vals per lane ----
#pragma unroll
            for (int h = 0; h < 2; h++) {
                float v[8];
#pragma unroll
                for (int bt = 0; bt < 4; bt++) {
                    v[2 * bt]     = acc[bt][2 * h];
                    v[2 * bt + 1] = acc[bt][2 * h + 1];
                }
                float mx = fmaxf(fmaxf(fmaxf(v[0], v[1]), fmaxf(v[2], v[3])),
                                 fmaxf(fmaxf(v[4], v[5]), fmaxf(v[6], v[7])));
                float mnew = fmaxf(mrun[h], mx);
                float ss = __expf(v[0] - mnew) + __expf(v[1] - mnew) +
                           __expf(v[2] - mnew) + __expf(v[3] - mnew) +
                           __expf(v[4] - mnew) + __expf(v[5] - mnew) +
                           __expf(v[6] - mnew) + __expf(v[7] - mnew);
                srun[h] = srun[h] * __expf(mrun[h] - mnew) + ss;
                mrun[h] = mnew;
            }
        }
    }

    // ---- merge across the 4 lanes sharing each row; write sfac ----
    if (tid < 256) {
#pragma unroll
        for (int h = 0; h < 2; h++) {
            float m = mrun[h], sv = srun[h];
#pragma unroll
            for (int d = 1; d < 4; d <<= 1) {
                float mo = __shfl_xor_sync(0xffffffffu, m, d);
                float so = __shfl_xor_sync(0xffffffffu, sv, d);
                float mn = fmaxf(m, mo);
                sv = sv * __expf(m - mn) + so * __expf(mo - mn);
                m = mn;
            }
            if ((L & 3) == 0) {
                int nl = w * 16 + h * 8 + (L >> 2);
                sfac[nl] = __expf(sdiag[nl] - m) / sv;
            }
        }
    }
    __syncthreads();

    // ---- store: out[c][n] = X[c][n] * fac[n] ----
    float* Ob = out + (size_t)b * CDIM * NDIM;
#pragma unroll 1
    for (int idx = tid; idx < 256 * 32; idx += 384) {
        int c = idx >> 5, g = idx & 31;
        float4 f = *(const float4*)&sfac[g * 4];
        float4 x = *(const float4*)(Xb + (size_t)c * NDIM + n0 + g * 4);
        x.x *= f.x; x.y *= f.y; x.z *= f.z; x.w *= f.w;
        *(float4*)(Ob + (size_t)c * NDIM + n0 + g * 4) = x;
    }
}

// ---------------- launch ----------------
extern "C" void kernel_launch(void* const* d_in, const int* in_sizes, int n_in,
                              void* d_out, int out_size) {
    const float* pts = (const float*)d_in[0];
    const float* Wq  = (const float*)d_in[1];
    const float* Wk  = (const float*)d_in[2];
    float* out = (float*)d_out;

    cudaFuncSetAttribute(attn_kernel, cudaFuncAttributeMaxDynamicSharedMemorySize, SMEM_SZ);

    mt_kernel<<<dim3(16, 16), dim3(16, 16)>>>(Wq, Wk);
    xt_kernel<<<dim3(NDIM / 32, CDIM / 32, BDIM), dim3(32, 8)>>>(pts);
    ymat_kernel<<<dim3(NDIM / BT, CDIM / BT, BDIM), 256>>>(pts);
    attn_kernel<<<dim3(NDIM / 128, BDIM), 384, SMEM_SZ>>>(pts, out);
}